// round 1
// baseline (speedup 1.0000x reference)
#include <cuda_runtime.h>
#include <math.h>

#define B_ 64
#define T_ 512
#define F_ 64
#define U_ 128
#define G_ 512   // 4*U

// ---------------- scratch (static device memory; no allocations) ----------------
__device__ float g_mask[B_ * T_];                       // 32768
__device__ float g_zx[2u * B_ * T_ * G_];               // 33.5M floats (reused layer1 then layer2)
__device__ float g_h1[B_ * T_ * 2 * U_];                // layer-1 hidden concat [b][t][2U]
__device__ float g_h2[B_ * 2 * U_];                     // layer-2 final hidden concat
__device__ float g_whT[4 * G_ * U_];                    // Wh transposed: [seg][col][k], seg = layer*2+dir

// ---------------- prep: mask + Wh transpose ----------------
__global__ void prep_kernel(const float* __restrict__ x,
                            const float* __restrict__ w1f, const float* __restrict__ w1b,
                            const float* __restrict__ w2f, const float* __restrict__ w2b) {
    int i = blockIdx.x * blockDim.x + threadIdx.x;
    if (i < B_ * T_) {
        const float4* row = (const float4*)(x + (size_t)i * F_);
        bool nz = false;
#pragma unroll
        for (int k = 0; k < F_ / 4; k++) {
            float4 v = row[k];
            nz = nz || (v.x != 0.f) || (v.y != 0.f) || (v.z != 0.f) || (v.w != 0.f);
        }
        g_mask[i] = nz ? 1.f : 0.f;
    }
    int j = i - B_ * T_;
    if (j >= 0 && j < 4 * G_ * U_) {
        int w = j >> 16;           // which weight (0..3)
        int r = j & 65535;         // index within [128][512]
        int k = r >> 9;            // row (0..127)
        int col = r & 511;         // col (0..511)
        const float* src = (w == 0) ? w1f : (w == 1) ? w1b : (w == 2) ? w2f : w2b;
        g_whT[w * (G_ * U_) + col * U_ + k] = src[r];
    }
}

// ---------------- tiled fp32 GEMM with bias: C[M,N] = A[M,K] @ W[K,N] + bias ----------------
// BM=BN=128, BK=16, 256 threads, 8x8 microtile. A selected: external ptr or g_h1.
__global__ __launch_bounds__(256) void sgemm_bias(
    const float* __restrict__ Aext, int useH1,
    const float* __restrict__ W, const float* __restrict__ bias,
    int dirOff, int M, int N, int K) {
    __shared__ float As[16][132];   // padded to reduce store conflicts, keeps 16B align
    __shared__ float Bs[16][128];
    const float* A = useH1 ? g_h1 : Aext;
    float* C = g_zx + (size_t)dirOff * B_ * T_ * G_;

    int tid = threadIdx.x;
    int nBase = blockIdx.x * 128;
    int mBase = blockIdx.y * 128;
    int tx = tid & 15, ty = tid >> 4;
    float acc[8][8];
#pragma unroll
    for (int i = 0; i < 8; i++)
#pragma unroll
        for (int j = 0; j < 8; j++) acc[i][j] = 0.f;

    for (int k0 = 0; k0 < K; k0 += 16) {
#pragma unroll
        for (int s = 0; s < 2; s++) {
            int slot = tid + s * 256;
            int row = slot >> 2, c4 = slot & 3;
            float4 v = *(const float4*)(A + (size_t)(mBase + row) * K + k0 + c4 * 4);
            As[c4 * 4 + 0][row] = v.x;
            As[c4 * 4 + 1][row] = v.y;
            As[c4 * 4 + 2][row] = v.z;
            As[c4 * 4 + 3][row] = v.w;
        }
#pragma unroll
        for (int s = 0; s < 2; s++) {
            int slot = tid + s * 256;
            int row = slot >> 5, c4 = slot & 31;
            *(float4*)(&Bs[row][c4 * 4]) =
                *(const float4*)(W + (size_t)(k0 + row) * N + nBase + c4 * 4);
        }
        __syncthreads();
#pragma unroll
        for (int k = 0; k < 16; k++) {
            float a[8], b[8];
            *(float4*)(a)     = *(const float4*)&As[k][ty * 8];
            *(float4*)(a + 4) = *(const float4*)&As[k][ty * 8 + 4];
            *(float4*)(b)     = *(const float4*)&Bs[k][tx * 8];
            *(float4*)(b + 4) = *(const float4*)&Bs[k][tx * 8 + 4];
#pragma unroll
            for (int i = 0; i < 8; i++)
#pragma unroll
                for (int j = 0; j < 8; j++) acc[i][j] = fmaf(a[i], b[j], acc[i][j]);
        }
        __syncthreads();
    }
#pragma unroll
    for (int i = 0; i < 8; i++) {
        int row = mBase + ty * 8 + i;
#pragma unroll
        for (int j = 0; j < 8; j += 4) {
            int col = nBase + tx * 8 + j;
            float4 o;
            o.x = acc[i][j + 0] + bias[col + 0];
            o.y = acc[i][j + 1] + bias[col + 1];
            o.z = acc[i][j + 2] + bias[col + 2];
            o.w = acc[i][j + 3] + bias[col + 3];
            *(float4*)(C + (size_t)row * N + col) = o;
        }
    }
}

// ---------------- recurrent LSTM scan ----------------
__device__ __forceinline__ float sigf(float x) { return 1.f / (1.f + __expf(-x)); }

// 64 blocks: dir = blk>>5, batch pair = (blk&31)*2. 512 threads: one per gate column.
__global__ __launch_bounds__(512) void lstm_scan(int layer) {
    int bIdx = blockIdx.x;
    int dir = bIdx >> 5;
    int b0 = (bIdx & 31) * 2;
    __shared__ float sh_h[2][128];
    __shared__ float sh_z[2][512];
    int tid = threadIdx.x;
    if (tid < 256) sh_h[tid >> 7][tid & 127] = 0.f;
    __syncthreads();

    const float* wcol = g_whT + ((size_t)((layer * 2 + dir) * G_ + tid)) * U_;  // 128 contiguous
    const float* zbase = g_zx + ((size_t)(dir * B_ + b0) * T_) * G_;
    float c_reg = 0.f;
    int nb = tid >> 7, u = tid & 127;

    for (int t = 0; t < T_; t++) {
        int te = dir ? (T_ - 1 - t) : t;
        const float* z0 = zbase + (size_t)te * G_;
        float acc0 = z0[tid];
        float acc1 = z0[(size_t)T_ * G_ + tid];   // batch b0+1
        const float4* w4 = (const float4*)wcol;
        const float4* ha = (const float4*)sh_h[0];
        const float4* hb = (const float4*)sh_h[1];
#pragma unroll
        for (int k = 0; k < 32; k++) {
            float4 w = w4[k];
            float4 a = ha[k];
            float4 b = hb[k];
            acc0 += w.x * a.x + w.y * a.y + w.z * a.z + w.w * a.w;
            acc1 += w.x * b.x + w.y * b.y + w.z * b.z + w.w * b.w;
        }
        sh_z[0][tid] = acc0;
        sh_z[1][tid] = acc1;
        __syncthreads();
        if (tid < 256) {
            float zi = sh_z[nb][u];
            float zf = sh_z[nb][128 + u];
            float zg = sh_z[nb][256 + u];
            float zo = sh_z[nb][384 + u];
            float cn = sigf(zf) * c_reg + sigf(zi) * tanhf(zg);
            float hn = sigf(zo) * tanhf(cn);
            float m = g_mask[(b0 + nb) * T_ + te];
            float hprev = sh_h[nb][u];
            bool mm = (m != 0.f);
            c_reg = mm ? cn : c_reg;
            float hnew = mm ? hn : hprev;
            sh_h[nb][u] = hnew;
            if (layer == 0)
                g_h1[((size_t)(b0 + nb) * T_ + te) * (2 * U_) + dir * U_ + u] = hnew;
        }
        __syncthreads();
    }
    if (layer == 1 && tid < 256)
        g_h2[(b0 + nb) * (2 * U_) + dir * U_ + u] = sh_h[nb][u];
}

// ---------------- head: out = sigmoid(relu(h2 @ Wd + bd) @ Ws + bs) ----------------
__global__ __launch_bounds__(128) void head_kernel(
    const float* __restrict__ Wd, const float* __restrict__ bd,
    const float* __restrict__ Ws, const float* __restrict__ bs,
    float* __restrict__ out) {
    int b = blockIdx.x, u = threadIdx.x;
    float acc = bd[u];
    const float* h2 = g_h2 + b * (2 * U_);
#pragma unroll 8
    for (int j = 0; j < 2 * U_; j++) acc = fmaf(h2[j], Wd[j * U_ + u], acc);
    acc = fmaxf(acc, 0.f);
    float s = acc * Ws[u];
    __shared__ float red[128];
    red[u] = s;
    __syncthreads();
    for (int off = 64; off; off >>= 1) {
        if (u < off) red[u] += red[u + off];
        __syncthreads();
    }
    if (u == 0) out[b] = 1.f / (1.f + expf(-(red[0] + bs[0])));
}

// ---------------- launch ----------------
extern "C" void kernel_launch(void* const* d_in, const int* in_sizes, int n_in,
                              void* d_out, int out_size) {
    const float* x    = (const float*)d_in[0];
    const float* W1fi = (const float*)d_in[1];
    const float* W1fh = (const float*)d_in[2];
    const float* b1f  = (const float*)d_in[3];
    const float* W1bi = (const float*)d_in[4];
    const float* W1bh = (const float*)d_in[5];
    const float* b1b  = (const float*)d_in[6];
    const float* W2fi = (const float*)d_in[7];
    const float* W2fh = (const float*)d_in[8];
    const float* b2f  = (const float*)d_in[9];
    const float* W2bi = (const float*)d_in[10];
    const float* W2bh = (const float*)d_in[11];
    const float* b2b  = (const float*)d_in[12];
    const float* Wd   = (const float*)d_in[13];
    const float* bd   = (const float*)d_in[14];
    const float* Ws   = (const float*)d_in[15];
    const float* bs   = (const float*)d_in[16];

    // prep: mask (32768) + 4 Wh transposes (262144)
    int prepWork = B_ * T_ + 4 * G_ * U_;
    prep_kernel<<<(prepWork + 255) / 256, 256>>>(x, W1fh, W1bh, W2fh, W2bh);

    dim3 ggrid(G_ / 128, (B_ * T_) / 128);  // (4, 256)

    // layer-1 input projections
    sgemm_bias<<<ggrid, 256>>>(x, 0, W1fi, b1f, 0, B_ * T_, G_, F_);
    sgemm_bias<<<ggrid, 256>>>(x, 0, W1bi, b1b, 1, B_ * T_, G_, F_);
    lstm_scan<<<64, 512>>>(0);

    // layer-2 input projections (reuse g_zx)
    sgemm_bias<<<ggrid, 256>>>(nullptr, 1, W2fi, b2f, 0, B_ * T_, G_, 2 * U_);
    sgemm_bias<<<ggrid, 256>>>(nullptr, 1, W2bi, b2b, 1, B_ * T_, G_, 2 * U_);
    lstm_scan<<<64, 512>>>(1);

    head_kernel<<<64, 128>>>(Wd, bd, Ws, bs, (float*)d_out);
}

// round 3
// speedup vs baseline: 2.3340x; 2.3340x over previous
#include <cuda_runtime.h>
#include <math.h>

#define B_ 64
#define T_ 512
#define F_ 64
#define U_ 128
#define G_ 512   // 4*U

// ---------------- scratch (static device memory; no allocations) ----------------
__device__ float g_mask[B_ * T_];                       // 32768
__device__ float g_zx[2u * B_ * T_ * G_];               // 33.5M floats (layer1 then layer2)
__device__ float g_h1[B_ * T_ * 2 * U_];                // layer-1 hidden concat [b][t][2U]
__device__ float g_h2[B_ * 2 * U_];                     // layer-2 final hidden concat
// packed recurrent weights: [seg][(k>>2)*2048 + col*4 + (k&3)], seg = layer*2+dir
__device__ float g_wpk[4 * G_ * U_];

// ---------------- f32x2 helpers ----------------
#define FMA2(acc, a, b) asm("fma.rn.f32x2 %0, %1, %2, %0;" : "+l"(acc) : "l"(a), "l"(b))

__device__ __forceinline__ float f32x2_sum(unsigned long long v) {
    unsigned lo, hi;
    asm("mov.b64 {%0, %1}, %2;" : "=r"(lo), "=r"(hi) : "l"(v));
    return __uint_as_float(lo) + __uint_as_float(hi);
}

// ---------------- prep: mask + weight packing ----------------
__global__ void prep_kernel(const float* __restrict__ x,
                            const float* __restrict__ w1f, const float* __restrict__ w1b,
                            const float* __restrict__ w2f, const float* __restrict__ w2b) {
    int i = blockIdx.x * blockDim.x + threadIdx.x;
    if (i < B_ * T_) {
        const float4* row = (const float4*)(x + (size_t)i * F_);
        bool nz = false;
#pragma unroll
        for (int k = 0; k < F_ / 4; k++) {
            float4 v = row[k];
            nz = nz || (v.x != 0.f) || (v.y != 0.f) || (v.z != 0.f) || (v.w != 0.f);
        }
        g_mask[i] = nz ? 1.f : 0.f;
    }
    int j = i - B_ * T_;
    if (j >= 0 && j < 4 * G_ * U_) {
        int w = j >> 16;           // which weight (0..3)
        int r = j & 65535;         // index within [128][512]
        int k = r >> 9;            // k row (0..127)
        int col = r & 511;         // gate col (0..511)
        const float* src = (w == 0) ? w1f : (w == 1) ? w1b : (w == 2) ? w2f : w2b;
        g_wpk[w * (G_ * U_) + (k >> 2) * 2048 + col * 4 + (k & 3)] = src[r];
    }
}

// ---------------- tiled fp32 GEMM with bias: C[M,N] = A[M,K] @ W[K,N] + bias ----------------
__global__ __launch_bounds__(256) void sgemm_bias(
    const float* __restrict__ Aext, int useH1,
    const float* __restrict__ W, const float* __restrict__ bias,
    int dirOff, int M, int N, int K) {
    __shared__ float As[16][132];
    __shared__ float Bs[16][128];
    const float* A = useH1 ? g_h1 : Aext;
    float* C = g_zx + (size_t)dirOff * B_ * T_ * G_;

    int tid = threadIdx.x;
    int nBase = blockIdx.x * 128;
    int mBase = blockIdx.y * 128;
    int tx = tid & 15, ty = tid >> 4;
    float acc[8][8];
#pragma unroll
    for (int i = 0; i < 8; i++)
#pragma unroll
        for (int j = 0; j < 8; j++) acc[i][j] = 0.f;

    for (int k0 = 0; k0 < K; k0 += 16) {
#pragma unroll
        for (int s = 0; s < 2; s++) {
            int slot = tid + s * 256;
            int row = slot >> 2, c4 = slot & 3;
            float4 v = *(const float4*)(A + (size_t)(mBase + row) * K + k0 + c4 * 4);
            As[c4 * 4 + 0][row] = v.x;
            As[c4 * 4 + 1][row] = v.y;
            As[c4 * 4 + 2][row] = v.z;
            As[c4 * 4 + 3][row] = v.w;
        }
#pragma unroll
        for (int s = 0; s < 2; s++) {
            int slot = tid + s * 256;
            int row = slot >> 5, c4 = slot & 31;
            *(float4*)(&Bs[row][c4 * 4]) =
                *(const float4*)(W + (size_t)(k0 + row) * N + nBase + c4 * 4);
        }
        __syncthreads();
#pragma unroll
        for (int k = 0; k < 16; k++) {
            float a[8], b[8];
            *(float4*)(a)     = *(const float4*)&As[k][ty * 8];
            *(float4*)(a + 4) = *(const float4*)&As[k][ty * 8 + 4];
            *(float4*)(b)     = *(const float4*)&Bs[k][tx * 8];
            *(float4*)(b + 4) = *(const float4*)&Bs[k][tx * 8 + 4];
#pragma unroll
            for (int i = 0; i < 8; i++)
#pragma unroll
                for (int j = 0; j < 8; j++) acc[i][j] = fmaf(a[i], b[j], acc[i][j]);
        }
        __syncthreads();
    }
#pragma unroll
    for (int i = 0; i < 8; i++) {
        int row = mBase + ty * 8 + i;
#pragma unroll
        for (int j = 0; j < 8; j += 4) {
            int col = nBase + tx * 8 + j;
            float4 o;
            o.x = acc[i][j + 0] + bias[col + 0];
            o.y = acc[i][j + 1] + bias[col + 1];
            o.z = acc[i][j + 2] + bias[col + 2];
            o.w = acc[i][j + 3] + bias[col + 3];
            *(float4*)(C + (size_t)row * N + col) = o;
        }
    }
}

// ---------------- recurrent LSTM scan ----------------
// 64 blocks: dir = blk>>5, batch pair b0 = (blk&31)*2. 1024 threads:
//   matvec: c = tid&511 (gate col), kh = tid>>9 (k-half of 64)
//   elementwise: tid<256, eb = tid>>7, eu = tid&127
__global__ __launch_bounds__(1024) void lstm_scan(int layer) {
    int dir = blockIdx.x >> 5;
    int b0 = (blockIdx.x & 31) * 2;
    int tid = threadIdx.x;
    int c = tid & 511;
    int kh = tid >> 9;

    __shared__ __align__(16) float sh_h[2][128];
    __shared__ __align__(16) float2 sh_part[2][512];   // [kh][col] = (b0, b1) partials

    if (tid < 256) sh_h[tid >> 7][tid & 127] = 0.f;
    __syncthreads();

    int seg = layer * 2 + dir;
    const float* wseg = g_wpk + (size_t)seg * 65536 + (size_t)(16 * kh) * 2048 + c * 4;
    const float* hbase0 = &sh_h[0][64 * kh];
    const float* hbase1 = &sh_h[1][64 * kh];

    // elementwise per-thread state + prefetched z/mask
    int eb = tid >> 7, eu = tid & 127;
    const float* zrow = g_zx + ((size_t)dir * B_ + (b0 + eb)) * T_ * G_;
    float c_state = 0.f;
    float zi = 0, zf = 0, zg = 0, zo = 0, mcur = 0;
    if (tid < 256) {
        int te0 = dir ? (T_ - 1) : 0;
        const float* zp = zrow + (size_t)te0 * G_;
        zi = zp[eu]; zf = zp[128 + eu]; zg = zp[256 + eu]; zo = zp[384 + eu];
        mcur = g_mask[(b0 + eb) * T_ + te0];
    }

    for (int t = 0; t < T_; t++) {
        int te = dir ? (T_ - 1 - t) : t;

        unsigned long long acc0 = 0ull, acc1 = 0ull;   // f32x2 {0,0}
#pragma unroll
        for (int i = 0; i < 16; i++) {
            ulonglong2 wp = *(const ulonglong2*)(wseg + i * 2048);      // w[k..k+3] for col c
            ulonglong2 h0 = *(const ulonglong2*)(hbase0 + i * 4);       // h_b0[k..k+3]
            ulonglong2 h1 = *(const ulonglong2*)(hbase1 + i * 4);       // h_b1[k..k+3]
            FMA2(acc0, wp.x, h0.x);
            FMA2(acc0, wp.y, h0.y);
            FMA2(acc1, wp.x, h1.x);
            FMA2(acc1, wp.y, h1.y);
        }
        sh_part[kh][c] = make_float2(f32x2_sum(acc0), f32x2_sum(acc1));
        __syncthreads();

        if (tid < 256) {
            // prefetch next step's z + mask (hides DRAM latency behind next matvec)
            float nzi = 0, nzf = 0, nzg = 0, nzo = 0, nm = 0;
            if (t + 1 < T_) {
                int tn = dir ? (T_ - 2 - t) : (t + 1);
                const float* zp = zrow + (size_t)tn * G_;
                nzi = zp[eu]; nzf = zp[128 + eu]; nzg = zp[256 + eu]; nzo = zp[384 + eu];
                nm = g_mask[(b0 + eb) * T_ + tn];
            }
            const float* pp = (const float*)sh_part;   // [kh*512 + col][2]
#define PSUM(g) (pp[((g)*128 + eu) * 2 + eb] + pp[(512 + (g)*128 + eu) * 2 + eb])
            float vi = zi + PSUM(0);
            float vf = zf + PSUM(1);
            float vg = zg + PSUM(2);
            float vo = zo + PSUM(3);
#undef PSUM
            float si = 1.f / (1.f + __expf(-vi));
            float sf = 1.f / (1.f + __expf(-vf));
            float so = 1.f / (1.f + __expf(-vo));
            float cn = sf * c_state + si * tanhf(vg);
            float hn = so * tanhf(cn);
            float hprev = sh_h[eb][eu];
            bool mm = (mcur != 0.f);
            c_state = mm ? cn : c_state;
            float hnew = mm ? hn : hprev;
            sh_h[eb][eu] = hnew;
            if (layer == 0)
                g_h1[((size_t)(b0 + eb) * T_ + te) * (2 * U_) + dir * U_ + eu] = hnew;
            zi = nzi; zf = nzf; zg = nzg; zo = nzo; mcur = nm;
        }
        __syncthreads();
    }

    if (layer == 1 && tid < 256)
        g_h2[(b0 + eb) * (2 * U_) + dir * U_ + eu] = sh_h[eb][eu];
}

// ---------------- head: out = sigmoid(relu(h2 @ Wd + bd) @ Ws + bs) ----------------
__global__ __launch_bounds__(128) void head_kernel(
    const float* __restrict__ Wd, const float* __restrict__ bd,
    const float* __restrict__ Ws, const float* __restrict__ bs,
    float* __restrict__ out) {
    int b = blockIdx.x, u = threadIdx.x;
    float acc = bd[u];
    const float* h2 = g_h2 + b * (2 * U_);
#pragma unroll 8
    for (int j = 0; j < 2 * U_; j++) acc = fmaf(h2[j], Wd[j * U_ + u], acc);
    acc = fmaxf(acc, 0.f);
    float s = acc * Ws[u];
    __shared__ float red[128];
    red[u] = s;
    __syncthreads();
    for (int off = 64; off; off >>= 1) {
        if (u < off) red[u] += red[u + off];
        __syncthreads();
    }
    if (u == 0) out[b] = 1.f / (1.f + expf(-(red[0] + bs[0])));
}

// ---------------- launch ----------------
extern "C" void kernel_launch(void* const* d_in, const int* in_sizes, int n_in,
                              void* d_out, int out_size) {
    const float* x    = (const float*)d_in[0];
    const float* W1fi = (const float*)d_in[1];
    const float* W1fh = (const float*)d_in[2];
    const float* b1f  = (const float*)d_in[3];
    const float* W1bi = (const float*)d_in[4];
    const float* W1bh = (const float*)d_in[5];
    const float* b1b  = (const float*)d_in[6];
    const float* W2fi = (const float*)d_in[7];
    const float* W2fh = (const float*)d_in[8];
    const float* b2f  = (const float*)d_in[9];
    const float* W2bi = (const float*)d_in[10];
    const float* W2bh = (const float*)d_in[11];
    const float* b2b  = (const float*)d_in[12];
    const float* Wd   = (const float*)d_in[13];
    const float* bd   = (const float*)d_in[14];
    const float* Ws   = (const float*)d_in[15];
    const float* bs   = (const float*)d_in[16];

    int prepWork = B_ * T_ + 4 * G_ * U_;
    prep_kernel<<<(prepWork + 255) / 256, 256>>>(x, W1fh, W1bh, W2fh, W2bh);

    dim3 ggrid(G_ / 128, (B_ * T_) / 128);  // (4, 256)

    // layer-1 input projections
    sgemm_bias<<<ggrid, 256>>>(x, 0, W1fi, b1f, 0, B_ * T_, G_, F_);
    sgemm_bias<<<ggrid, 256>>>(x, 0, W1bi, b1b, 1, B_ * T_, G_, F_);
    lstm_scan<<<64, 1024>>>(0);

    // layer-2 input projections (reuse g_zx)
    sgemm_bias<<<ggrid, 256>>>(nullptr, 1, W2fi, b2f, 0, B_ * T_, G_, 2 * U_);
    sgemm_bias<<<ggrid, 256>>>(nullptr, 1, W2bi, b2b, 1, B_ * T_, G_, 2 * U_);
    lstm_scan<<<64, 1024>>>(1);

    head_kernel<<<64, 128>>>(Wd, bd, Ws, bs, (float*)d_out);
}

// round 4
// speedup vs baseline: 4.6117x; 1.9759x over previous
#include <cuda_runtime.h>
#include <math.h>
#include <stdint.h>

#define B_ 64
#define T_ 512
#define F_ 64
#define U_ 128
#define G_ 512   // 4*U

// ---------------- scratch (static device memory; no allocations) ----------------
__device__ float g_mask[B_ * T_];                       // 32768
__device__ float g_zx[2u * B_ * T_ * G_];               // 33.5M floats (layer1 then layer2)
__device__ float g_h1[B_ * T_ * 2 * U_];                // layer-1 hidden concat [b][t][2U]
__device__ float g_h2[B_ * 2 * U_];                     // layer-2 final hidden concat
// packed recurrent weights: [seg][(k>>2)*2048 + col*4 + (k&3)], seg = layer*2+dir
__device__ float g_wpk[4 * G_ * U_];

// ---------------- helpers ----------------
#define FMA2(acc, a, b) asm("fma.rn.f32x2 %0, %1, %2, %0;" : "+l"(acc) : "l"(a), "l"(b))

__device__ __forceinline__ float f32x2_sum(unsigned long long v) {
    unsigned lo, hi;
    asm("mov.b64 {%0, %1}, %2;" : "=r"(lo), "=r"(hi) : "l"(v));
    return __uint_as_float(lo) + __uint_as_float(hi);
}
__device__ __forceinline__ uint32_t s2u(const void* p) {
    uint32_t a;
    asm("{ .reg .u64 t; cvta.to.shared.u64 t, %1; cvt.u32.u64 %0, t; }" : "=r"(a) : "l"(p));
    return a;
}
__device__ __forceinline__ uint32_t ctarank() {
    uint32_t r;
    asm("mov.u32 %0, %%cluster_ctarank;" : "=r"(r));
    return r;
}

// ---------------- prep: mask + weight packing ----------------
__global__ void prep_kernel(const float* __restrict__ x,
                            const float* __restrict__ w1f, const float* __restrict__ w1b,
                            const float* __restrict__ w2f, const float* __restrict__ w2b) {
    int i = blockIdx.x * blockDim.x + threadIdx.x;
    if (i < B_ * T_) {
        const float4* row = (const float4*)(x + (size_t)i * F_);
        bool nz = false;
#pragma unroll
        for (int k = 0; k < F_ / 4; k++) {
            float4 v = row[k];
            nz = nz || (v.x != 0.f) || (v.y != 0.f) || (v.z != 0.f) || (v.w != 0.f);
        }
        g_mask[i] = nz ? 1.f : 0.f;
    }
    int j = i - B_ * T_;
    if (j >= 0 && j < 4 * G_ * U_) {
        int w = j >> 16;           // which weight (0..3)
        int r = j & 65535;         // index within [128][512]
        int k = r >> 9;            // k row (0..127)
        int col = r & 511;         // gate col (0..511)
        const float* src = (w == 0) ? w1f : (w == 1) ? w1b : (w == 2) ? w2f : w2b;
        g_wpk[w * (G_ * U_) + (k >> 2) * 2048 + col * 4 + (k & 3)] = src[r];
    }
}

// ---------------- tiled fp32 GEMM with bias ----------------
__global__ __launch_bounds__(256) void sgemm_bias(
    const float* __restrict__ Aext, int useH1,
    const float* __restrict__ W, const float* __restrict__ bias,
    int dirOff, int M, int N, int K) {
    __shared__ float As[16][132];
    __shared__ float Bs[16][128];
    const float* A = useH1 ? g_h1 : Aext;
    float* C = g_zx + (size_t)dirOff * B_ * T_ * G_;

    int tid = threadIdx.x;
    int nBase = blockIdx.x * 128;
    int mBase = blockIdx.y * 128;
    int tx = tid & 15, ty = tid >> 4;
    float acc[8][8];
#pragma unroll
    for (int i = 0; i < 8; i++)
#pragma unroll
        for (int j = 0; j < 8; j++) acc[i][j] = 0.f;

    for (int k0 = 0; k0 < K; k0 += 16) {
#pragma unroll
        for (int s = 0; s < 2; s++) {
            int slot = tid + s * 256;
            int row = slot >> 2, c4 = slot & 3;
            float4 v = *(const float4*)(A + (size_t)(mBase + row) * K + k0 + c4 * 4);
            As[c4 * 4 + 0][row] = v.x;
            As[c4 * 4 + 1][row] = v.y;
            As[c4 * 4 + 2][row] = v.z;
            As[c4 * 4 + 3][row] = v.w;
        }
#pragma unroll
        for (int s = 0; s < 2; s++) {
            int slot = tid + s * 256;
            int row = slot >> 5, c4 = slot & 31;
            *(float4*)(&Bs[row][c4 * 4]) =
                *(const float4*)(W + (size_t)(k0 + row) * N + nBase + c4 * 4);
        }
        __syncthreads();
#pragma unroll
        for (int k = 0; k < 16; k++) {
            float a[8], b[8];
            *(float4*)(a)     = *(const float4*)&As[k][ty * 8];
            *(float4*)(a + 4) = *(const float4*)&As[k][ty * 8 + 4];
            *(float4*)(b)     = *(const float4*)&Bs[k][tx * 8];
            *(float4*)(b + 4) = *(const float4*)&Bs[k][tx * 8 + 4];
#pragma unroll
            for (int i = 0; i < 8; i++)
#pragma unroll
                for (int j = 0; j < 8; j++) acc[i][j] = fmaf(a[i], b[j], acc[i][j]);
        }
        __syncthreads();
    }
#pragma unroll
    for (int i = 0; i < 8; i++) {
        int row = mBase + ty * 8 + i;
#pragma unroll
        for (int j = 0; j < 8; j += 4) {
            int col = nBase + tx * 8 + j;
            float4 o;
            o.x = acc[i][j + 0] + bias[col + 0];
            o.y = acc[i][j + 1] + bias[col + 1];
            o.z = acc[i][j + 2] + bias[col + 2];
            o.w = acc[i][j + 3] + bias[col + 3];
            *(float4*)(C + (size_t)row * N + col) = o;
        }
    }
}

// ---------------- recurrent LSTM scan: cluster-2, register-resident weights ----------------
// 128 CTAs, cluster (2,1,1). cid = blockIdx.x>>1: dir = cid>>5, b0 = (cid&31)*2.
// Each CTA owns 256 gate cols (gc = rank*256 + c). 512 threads: c = tid&255, kh = tid>>8.
// Per thread: 64 weights (16 ulonglong2) register-resident. Gate halves exchanged per
// step via st.shared::cluster + mbarrier (double-buffered).
__global__ __launch_bounds__(512, 1) __cluster_dims__(2, 1, 1)
void lstm_scan(int layer) {
    int tid = threadIdx.x;
    uint32_t rank = ctarank();
    uint32_t peer = rank ^ 1u;
    int cid = blockIdx.x >> 1;
    int dir = cid >> 5;
    int b0 = (cid & 31) * 2;

    __shared__ __align__(16) float sh_h[2][128];            // [batch][u]
    __shared__ __align__(16) float2 sh_part[2][256];        // [kh][c] = (b0,b1)
    __shared__ __align__(16) float gbuf[2][512][2];         // [par][gc][batch]
    __shared__ __align__(8) unsigned long long mbar[2];

    int c = tid & 255;
    int kh = tid >> 8;
    int gc = (int)rank * 256 + c;
    int seg = layer * 2 + dir;

    // ---- load this thread's 64 weights into registers (once) ----
    ulonglong2 warr[16];
    {
        const float* wb = g_wpk + (size_t)seg * 65536 + (size_t)(16 * kh) * 2048 + gc * 4;
#pragma unroll
        for (int i = 0; i < 16; i++) warr[i] = *(const ulonglong2*)(wb + i * 2048);
    }

    uint32_t mbar0 = s2u(&mbar[0]);
    uint32_t mbar1 = s2u(&mbar[1]);
    uint32_t gbuf0 = s2u(&gbuf[0][0][0]);

    if (tid == 0) {
        asm volatile("mbarrier.init.shared.b64 [%0], %1;" :: "r"(mbar0), "r"(256) : "memory");
        asm volatile("mbarrier.init.shared.b64 [%0], %1;" :: "r"(mbar1), "r"(256) : "memory");
    }
    if (tid < 256) sh_h[tid >> 7][tid & 127] = 0.f;
    __syncthreads();
    asm volatile("barrier.cluster.arrive.aligned;" ::: "memory");
    asm volatile("barrier.cluster.wait.aligned;" ::: "memory");

    // elementwise identity (threads tid<256): unit eu of batch eb
    int eu = tid & 127, eb = tid >> 7;
    float c_state = 0.f;

    // z prefetch (writer role: col gc, both batches of the pair)
    const float* zcol = g_zx + ((size_t)dir * B_ + b0) * T_ * G_ + gc;
    float zpre0 = 0.f, zpre1 = 0.f, mpre = 0.f;
    if (tid < 256) {
        int te0 = dir ? (T_ - 1) : 0;
        zpre0 = zcol[(size_t)te0 * G_];
        zpre1 = zcol[(size_t)T_ * G_ + (size_t)te0 * G_];
        mpre = g_mask[(b0 + eb) * T_ + te0];
    }

    const float* hb0 = &sh_h[0][64 * kh];
    const float* hb1 = &sh_h[1][64 * kh];

    for (int t = 0; t < T_; t++) {
        int te = dir ? (T_ - 1 - t) : t;

        // ---- matvec: h @ Wh for this CTA's 256 cols, weights from registers ----
        unsigned long long acc0 = 0ull, acc1 = 0ull;
#pragma unroll
        for (int i = 0; i < 16; i++) {
            ulonglong2 w = warr[i];
            ulonglong2 h0 = *(const ulonglong2*)(hb0 + i * 4);
            ulonglong2 h1 = *(const ulonglong2*)(hb1 + i * 4);
            FMA2(acc0, w.x, h0.x); FMA2(acc0, w.y, h0.y);
            FMA2(acc1, w.x, h1.x); FMA2(acc1, w.y, h1.y);
        }
        sh_part[kh][c] = make_float2(f32x2_sum(acc0), f32x2_sum(acc1));
        __syncthreads();

        int par = t & 1;
        if (tid < 256) {
            // combine k-halves + zx bias; publish to own + peer gbuf
            float2 pa = sh_part[0][c], pb = sh_part[1][c];
            float z0 = zpre0 + pa.x + pb.x;
            float z1 = zpre1 + pa.y + pb.y;
            gbuf[par][gc][0] = z0;
            gbuf[par][gc][1] = z1;
            unsigned long long pkt;
            asm("mov.b64 %0, {%1, %2};" : "=l"(pkt)
                : "r"(__float_as_uint(z0)), "r"(__float_as_uint(z1)));
            uint32_t laddr = gbuf0 + (uint32_t)(par * 512 + gc) * 8u;
            asm volatile(
                "{ .reg .b32 ra; mapa.shared::cluster.u32 ra, %0, %1; "
                "st.shared::cluster.b64 [ra], %2; }"
                :: "r"(laddr), "r"(peer), "l"(pkt) : "memory");
            uint32_t mb = par ? mbar1 : mbar0;
            asm volatile(
                "{ .reg .b32 ra; mapa.shared::cluster.u32 ra, %0, %1; "
                "mbarrier.arrive.release.cluster.shared::cluster.b64 _, [ra]; }"
                :: "r"(mb), "r"(peer) : "memory");

            // prefetch next step's z/mask (hides latency behind peer wait)
            float nz0 = 0.f, nz1 = 0.f, nm = 0.f;
            if (t + 1 < T_) {
                int tn = dir ? (T_ - 2 - t) : (t + 1);
                nz0 = zcol[(size_t)tn * G_];
                nz1 = zcol[(size_t)T_ * G_ + (size_t)tn * G_];
                nm = g_mask[(b0 + eb) * T_ + tn];
            }

            // own-half gbuf visibility among these 256 threads
            asm volatile("bar.sync 1, 256;" ::: "memory");

            // wait for peer half (acquire, cluster scope)
            uint32_t parity = (uint32_t)((t >> 1) & 1);
            uint32_t done;
            asm volatile(
                "{\n\t.reg .pred P;\n\t"
                "mbarrier.try_wait.parity.acquire.cluster.shared::cta.b64 P, [%1], %2;\n\t"
                "selp.b32 %0, 1, 0, P;\n\t}"
                : "=r"(done) : "r"(mb), "r"(parity) : "memory");
            if (!done) {
                asm volatile(
                    "{\n\t.reg .pred P;\n"
                    "LW%=:\n\t"
                    "mbarrier.try_wait.parity.acquire.cluster.shared::cta.b64 P, [%0], %1, 0x989680;\n\t"
                    "@!P bra LW%=;\n\t}"
                    :: "r"(mb), "r"(parity) : "memory");
            }

            // ---- elementwise LSTM cell (redundant on both CTAs; keeps h local) ----
            float vi = gbuf[par][eu][eb];
            float vf = gbuf[par][128 + eu][eb];
            float vg = gbuf[par][256 + eu][eb];
            float vo = gbuf[par][384 + eu][eb];
            float si = 1.f / (1.f + __expf(-vi));
            float sf = 1.f / (1.f + __expf(-vf));
            float so = 1.f / (1.f + __expf(-vo));
            float cn = sf * c_state + si * tanhf(vg);
            float hn = so * tanhf(cn);
            float hprev = sh_h[eb][eu];
            bool mm = (mpre != 0.f);
            c_state = mm ? cn : c_state;
            float hnew = mm ? hn : hprev;
            sh_h[eb][eu] = hnew;
            if (layer == 0 && rank == 0)
                g_h1[((size_t)(b0 + eb) * T_ + te) * (2 * U_) + dir * U_ + eu] = hnew;
            zpre0 = nz0; zpre1 = nz1; mpre = nm;
        }
        __syncthreads();
    }

    if (layer == 1 && rank == 0 && tid < 256)
        g_h2[(b0 + eb) * (2 * U_) + dir * U_ + eu] = sh_h[eb][eu];

    asm volatile("barrier.cluster.arrive.aligned;" ::: "memory");
    asm volatile("barrier.cluster.wait.aligned;" ::: "memory");
}

// ---------------- head: out = sigmoid(relu(h2 @ Wd + bd) @ Ws + bs) ----------------
__global__ __launch_bounds__(128) void head_kernel(
    const float* __restrict__ Wd, const float* __restrict__ bd,
    const float* __restrict__ Ws, const float* __restrict__ bs,
    float* __restrict__ out) {
    int b = blockIdx.x, u = threadIdx.x;
    float acc = bd[u];
    const float* h2 = g_h2 + b * (2 * U_);
#pragma unroll 8
    for (int j = 0; j < 2 * U_; j++) acc = fmaf(h2[j], Wd[j * U_ + u], acc);
    acc = fmaxf(acc, 0.f);
    float s = acc * Ws[u];
    __shared__ float red[128];
    red[u] = s;
    __syncthreads();
    for (int off = 64; off; off >>= 1) {
        if (u < off) red[u] += red[u + off];
        __syncthreads();
    }
    if (u == 0) out[b] = 1.f / (1.f + expf(-(red[0] + bs[0])));
}

// ---------------- launch ----------------
extern "C" void kernel_launch(void* const* d_in, const int* in_sizes, int n_in,
                              void* d_out, int out_size) {
    const float* x    = (const float*)d_in[0];
    const float* W1fi = (const float*)d_in[1];
    const float* W1fh = (const float*)d_in[2];
    const float* b1f  = (const float*)d_in[3];
    const float* W1bi = (const float*)d_in[4];
    const float* W1bh = (const float*)d_in[5];
    const float* b1b  = (const float*)d_in[6];
    const float* W2fi = (const float*)d_in[7];
    const float* W2fh = (const float*)d_in[8];
    const float* b2f  = (const float*)d_in[9];
    const float* W2bi = (const float*)d_in[10];
    const float* W2bh = (const float*)d_in[11];
    const float* b2b  = (const float*)d_in[12];
    const float* Wd   = (const float*)d_in[13];
    const float* bd   = (const float*)d_in[14];
    const float* Ws   = (const float*)d_in[15];
    const float* bs   = (const float*)d_in[16];

    int prepWork = B_ * T_ + 4 * G_ * U_;
    prep_kernel<<<(prepWork + 255) / 256, 256>>>(x, W1fh, W1bh, W2fh, W2bh);

    dim3 ggrid(G_ / 128, (B_ * T_) / 128);  // (4, 256)

    // layer-1 input projections
    sgemm_bias<<<ggrid, 256>>>(x, 0, W1fi, b1f, 0, B_ * T_, G_, F_);
    sgemm_bias<<<ggrid, 256>>>(x, 0, W1bi, b1b, 1, B_ * T_, G_, F_);
    lstm_scan<<<128, 512>>>(0);

    // layer-2 input projections (reuse g_zx)
    sgemm_bias<<<ggrid, 256>>>(nullptr, 1, W2fi, b2f, 0, B_ * T_, G_, 2 * U_);
    sgemm_bias<<<ggrid, 256>>>(nullptr, 1, W2bi, b2b, 1, B_ * T_, G_, 2 * U_);
    lstm_scan<<<128, 512>>>(1);

    head_kernel<<<64, 128>>>(Wd, bd, Ws, bs, (float*)d_out);
}